// round 6
// baseline (speedup 1.0000x reference)
#include <cuda_runtime.h>
#include <cuda_bf16.h>
#include <cstdint>
#include <stdint.h>
#include <math.h>

#define BATCH 4
#define SEQ   2048
#define DM    1024
#define NH    16
#define HD    64
#define MTOT  (BATCH*SEQ)   // 8192

typedef unsigned int u32;

// Scratch (allocation-free rule: __device__ globals)
__device__ float g_Q [MTOT*DM];
__device__ float g_K [MTOT*DM];
__device__ float g_V [MTOT*DM];
__device__ float g_AO[MTOT*DM];

// ---------------------------------------------------------------------------
// helpers
// ---------------------------------------------------------------------------
__device__ __forceinline__ u32 f2tf(float f) {
    u32 u;
    asm("cvt.rna.tf32.f32 %0, %1;" : "=r"(u) : "f"(f));
    return u;
}

__device__ __forceinline__ void mma_tf32(float c[4], const u32 a[4],
                                         const u32 b[2]) {
    asm volatile(
        "mma.sync.aligned.m16n8k8.row.col.f32.tf32.tf32.f32 "
        "{%0,%1,%2,%3}, {%4,%5,%6,%7}, {%8,%9}, {%0,%1,%2,%3};"
        : "+f"(c[0]), "+f"(c[1]), "+f"(c[2]), "+f"(c[3])
        : "r"(a[0]), "r"(a[1]), "r"(a[2]), "r"(a[3]),
          "r"(b[0]), "r"(b[1]));
}

// ---------------------------------------------------------------------------
// GEMM mainloop: acc = A[M,1024] @ W[1024,1024]^T (einsum 'md,nd->mn').
// 128x128 CTA tile, k=16 per step, register double-buffer (LDG t+1 under
// compute t), one __syncthreads per k-tile. fp32 in, cvt.rna at STS.
// smem: 2 bufs x (A[128][20] + B[128][20]) u32 = 40960 B (static).
// 256 threads = 8 warps (4m x 2n), warp tile 32x64.
// ---------------------------------------------------------------------------
#define GP 20
#define GBUF (128*GP)

__device__ __forceinline__ void gemm_main(
    const float* __restrict__ A, const float* __restrict__ W,
    u32* __restrict__ sm, int m0, int n0, float acc[2][8][4])
{
    const int tid  = threadIdx.x;
    const int lane = tid & 31;
    const int wid  = tid >> 5;
    const int g    = lane >> 2;
    const int tg   = lane & 3;
    const int wm   = (wid >> 1) * 32;
    const int wn   = (wid & 1) * 64;

    const int row = tid >> 1;          // 0..127
    const int c0  = (tid & 1) * 8;     // 0 or 8

    const float* Ap = A + (size_t)(m0 + row) * DM + c0;
    const float* Wp = W + (size_t)(n0 + row) * DM + c0;

    #pragma unroll
    for (int mt = 0; mt < 2; mt++)
        #pragma unroll
        for (int nt = 0; nt < 8; nt++)
            #pragma unroll
            for (int r = 0; r < 4; r++) acc[mt][nt][r] = 0.0f;

    float4 ra0 = *(const float4*)(Ap);
    float4 ra1 = *(const float4*)(Ap + 4);
    float4 rw0 = *(const float4*)(Wp);
    float4 rw1 = *(const float4*)(Wp + 4);

    for (int t = 0; t < 64; t++) {
        u32* pA = sm + (t & 1) * GBUF;
        u32* pB = sm + 2 * GBUF + (t & 1) * GBUF;

        *(uint4*)&pA[row * GP + c0] =
            make_uint4(f2tf(ra0.x), f2tf(ra0.y), f2tf(ra0.z), f2tf(ra0.w));
        *(uint4*)&pA[row * GP + c0 + 4] =
            make_uint4(f2tf(ra1.x), f2tf(ra1.y), f2tf(ra1.z), f2tf(ra1.w));
        *(uint4*)&pB[row * GP + c0] =
            make_uint4(f2tf(rw0.x), f2tf(rw0.y), f2tf(rw0.z), f2tf(rw0.w));
        *(uint4*)&pB[row * GP + c0 + 4] =
            make_uint4(f2tf(rw1.x), f2tf(rw1.y), f2tf(rw1.z), f2tf(rw1.w));

        __syncthreads();

        if (t < 63) {
            const int k1 = (t + 1) * 16;
            ra0 = *(const float4*)(Ap + k1);
            ra1 = *(const float4*)(Ap + k1 + 4);
            rw0 = *(const float4*)(Wp + k1);
            rw1 = *(const float4*)(Wp + k1 + 4);
        }

        #pragma unroll
        for (int kk = 0; kk < 16; kk += 8) {
            u32 af[2][4], bf[8][2];
            #pragma unroll
            for (int mt = 0; mt < 2; mt++) {
                int r = wm + mt * 16 + g;
                af[mt][0] = pA[r * GP + kk + tg];
                af[mt][1] = pA[(r + 8) * GP + kk + tg];
                af[mt][2] = pA[r * GP + kk + tg + 4];
                af[mt][3] = pA[(r + 8) * GP + kk + tg + 4];
            }
            #pragma unroll
            for (int nt = 0; nt < 8; nt++) {
                int c = wn + nt * 8 + g;
                bf[nt][0] = pB[c * GP + kk + tg];
                bf[nt][1] = pB[c * GP + kk + tg + 4];
            }
            #pragma unroll
            for (int mt = 0; mt < 2; mt++)
                #pragma unroll
                for (int nt = 0; nt < 8; nt++)
                    mma_tf32(acc[mt][nt], af[mt], bf[nt]);
        }
    }
}

// Fused QKV projection: grid (8, 64, 3). z=0:Q(scale+RoPE) z=1:K(RoPE) z=2:V.
// Outputs scattered to [B,H,S,HD] as tf32-rounded bits (Q pre-scaled by 1/8).
__global__ void __launch_bounds__(256, 2) gemm_qkv(
    const float* __restrict__ X,
    const float* __restrict__ Wq, const float* __restrict__ Wk,
    const float* __restrict__ Wv,
    float* __restrict__ Qo, float* __restrict__ Ko, float* __restrict__ Vo)
{
    __shared__ __align__(16) u32 sm[4 * GBUF];
    const int z = blockIdx.z;
    const float* W = (z == 0) ? Wq : ((z == 1) ? Wk : Wv);
    float*       C = (z == 0) ? Qo : ((z == 1) ? Ko : Vo);
    const int m0 = blockIdx.y * 128;
    const int n0 = blockIdx.x * 128;

    float acc[2][8][4];
    gemm_main(X, W, sm, m0, n0, acc);

    const int lane = threadIdx.x & 31;
    const int wid  = threadIdx.x >> 5;
    const int g    = lane >> 2;
    const int tg   = lane & 3;
    const int wm   = (wid >> 1) * 32;
    const int wn   = (wid & 1) * 64;

    #pragma unroll
    for (int mt = 0; mt < 2; mt++) {
        #pragma unroll
        for (int nt = 0; nt < 8; nt++) {
            const int gn    = n0 + wn + nt * 8 + 2 * tg;  // even column
            const int rbase = m0 + wm + mt * 16 + g;
            const int h  = gn >> 6;
            const int d0 = gn & 63;
            const float invf =
                exp2f((float)d0 * (-13.287712379549449f / 64.0f));
            #pragma unroll
            for (int half = 0; half < 2; half++) {
                int m = rbase + half * 8;
                int b = m >> 11;
                int s = m & (SEQ - 1);
                float e = acc[mt][nt][half * 2];
                float o = acc[mt][nt][half * 2 + 1];
                if (z == 0) { e *= 0.125f; o *= 0.125f; }
                float r1, r2;
                if (z <= 1) {
                    float sn, cs;
                    sincosf((float)s * invf, &sn, &cs);
                    r1 = e * cs - o * sn;
                    r2 = e * sn + o * cs;
                } else { r1 = e; r2 = o; }
                size_t idx = (((size_t)(b * NH + h)) * SEQ + s) * HD + d0;
                *(float2*)(C + idx) =
                    make_float2(__uint_as_float(f2tf(r1)),
                                __uint_as_float(f2tf(r2)));
            }
        }
    }
}

// O projection: plain fp32 output.
__global__ void __launch_bounds__(256, 2) gemm_o(
    const float* __restrict__ A, const float* __restrict__ W,
    float* __restrict__ C)
{
    __shared__ __align__(16) u32 sm[4 * GBUF];
    const int m0 = blockIdx.y * 128;
    const int n0 = blockIdx.x * 128;

    float acc[2][8][4];
    gemm_main(A, W, sm, m0, n0, acc);

    const int lane = threadIdx.x & 31;
    const int wid  = threadIdx.x >> 5;
    const int g    = lane >> 2;
    const int tg   = lane & 3;
    const int wm   = (wid >> 1) * 32;
    const int wn   = (wid & 1) * 64;

    #pragma unroll
    for (int mt = 0; mt < 2; mt++) {
        #pragma unroll
        for (int nt = 0; nt < 8; nt++) {
            const int gn    = n0 + wn + nt * 8 + 2 * tg;
            const int rbase = m0 + wm + mt * 16 + g;
            *(float2*)(C + (size_t)rbase * DM + gn) =
                make_float2(acc[mt][nt][0], acc[mt][nt][1]);
            *(float2*)(C + (size_t)(rbase + 8) * DM + gn) =
                make_float2(acc[mt][nt][2], acc[mt][nt][3]);
        }
    }
}

// ---------------------------------------------------------------------------
// Flash attention (causal), mma.sync tf32. Q/K/V hold tf32-rounded bits
// (Q pre-scaled by 1/8). 256 threads / 8 warps, 128 q rows, K/V tiles of 64,
// single-buffered K/V (104 KB smem -> 2 CTAs/SM).
// ---------------------------------------------------------------------------
#define ATP 68
#define ATTN_SMEM ((128 + 64 + 64 + 128) * ATP * 4)   // 104448 B

__global__ void __launch_bounds__(256, 2) attn_k(
    const float* __restrict__ Q, const float* __restrict__ K,
    const float* __restrict__ V, float* __restrict__ O)
{
    extern __shared__ u32 smu[];
    u32* sQ = smu;                 // [128][ATP]
    u32* sK = sQ + 128 * ATP;      // [64][ATP]
    u32* sV = sK + 64  * ATP;      // [64][ATP]
    u32* sP = sV + 64  * ATP;      // [128][ATP] (warp-private rows)

    const int tid  = threadIdx.x;
    const int lane = tid & 31;
    const int wid  = tid >> 5;
    const int g    = lane >> 2;
    const int tg   = lane & 3;
    const int qw   = wid * 16;
    const int bh   = blockIdx.y;
    const int m0   = blockIdx.x * 128;

    const float* Qb = Q + ((size_t)bh * SEQ + m0) * HD;
    const float* Kb = K + (size_t)bh * SEQ * HD;
    const float* Vb = V + (size_t)bh * SEQ * HD;

    // Load Q tile (raw pre-rounded/pre-scaled bits)
    {
        const int lr  = tid >> 4;
        const int lc4 = (tid & 15) << 2;
        #pragma unroll
        for (int rr = 0; rr < 128; rr += 16) {
            uint4 v = *(const uint4*)(Qb + (size_t)(lr + rr) * HD + lc4);
            *(uint4*)&sQ[(lr + rr) * ATP + lc4] = v;
        }
    }

    float oacc[8][4];
    #pragma unroll
    for (int nt = 0; nt < 8; nt++)
        #pragma unroll
        for (int r = 0; r < 4; r++) oacc[nt][r] = 0.0f;
    float m_0 = -1e30f, m_1 = -1e30f, l0 = 0.0f, l1 = 0.0f;

    const int ntiles = 2 * blockIdx.x + 2;
    const int q0g = m0 + qw + g;
    const int q1g = q0g + 8;

    const int krow = tid >> 2;        // 0..63
    const int kc   = (tid & 3) * 16;  // col block

    for (int t = 0; t < ntiles; t++) {
        const int n0 = t * 64;
        __syncthreads();   // everyone done reading sK/sV of tile t-1

        #pragma unroll
        for (int jj = 0; jj < 4; jj++) {
            const int cc = kc + jj * 4;
            *(uint4*)&sK[krow * ATP + cc] =
                *(const uint4*)(Kb + (size_t)(n0 + krow) * HD + cc);
            *(uint4*)&sV[krow * ATP + cc] =
                *(const uint4*)(Vb + (size_t)(n0 + krow) * HD + cc);
        }
        __syncthreads();

        // S = Q @ K^T  (pre-scaled)
        float sf[8][4];
        #pragma unroll
        for (int nt = 0; nt < 8; nt++)
            #pragma unroll
            for (int r = 0; r < 4; r++) sf[nt][r] = 0.0f;

        #pragma unroll
        for (int kk = 0; kk < 8; kk++) {
            u32 af[4];
            af[0] = sQ[(qw + g    ) * ATP + kk * 8 + tg];
            af[1] = sQ[(qw + g + 8) * ATP + kk * 8 + tg];
            af[2] = sQ[(qw + g    ) * ATP + kk * 8 + tg + 4];
            af[3] = sQ[(qw + g + 8) * ATP + kk * 8 + tg + 4];
            #pragma unroll
            for (int nt = 0; nt < 8; nt++) {
                u32 bf[2];
                bf[0] = sK[(nt * 8 + g) * ATP + kk * 8 + tg];
                bf[1] = sK[(nt * 8 + g) * ATP + kk * 8 + tg + 4];
                mma_tf32(sf[nt], af, bf);
            }
        }

        // Causal mask (only tiles overlapping the diagonal)
        if (t >= 2 * (int)blockIdx.x) {
            #pragma unroll
            for (int nt = 0; nt < 8; nt++) {
                int jg = n0 + nt * 8 + 2 * tg;
                if (jg     > q0g) sf[nt][0] = -1e30f;
                if (jg + 1 > q0g) sf[nt][1] = -1e30f;
                if (jg     > q1g) sf[nt][2] = -1e30f;
                if (jg + 1 > q1g) sf[nt][3] = -1e30f;
            }
        }

        // Online softmax
        float mx0 = -1e30f, mx1 = -1e30f;
        #pragma unroll
        for (int nt = 0; nt < 8; nt++) {
            mx0 = fmaxf(mx0, fmaxf(sf[nt][0], sf[nt][1]));
            mx1 = fmaxf(mx1, fmaxf(sf[nt][2], sf[nt][3]));
        }
        mx0 = fmaxf(mx0, __shfl_xor_sync(0xffffffffu, mx0, 1));
        mx0 = fmaxf(mx0, __shfl_xor_sync(0xffffffffu, mx0, 2));
        mx1 = fmaxf(mx1, __shfl_xor_sync(0xffffffffu, mx1, 1));
        mx1 = fmaxf(mx1, __shfl_xor_sync(0xffffffffu, mx1, 2));

        float mn0 = fmaxf(m_0, mx0);
        float mn1 = fmaxf(m_1, mx1);
        float c0 = __expf(m_0 - mn0);
        float c1 = __expf(m_1 - mn1);
        m_0 = mn0; m_1 = mn1;

        float s0 = 0.0f, s1 = 0.0f;
        #pragma unroll
        for (int nt = 0; nt < 8; nt++) {
            float p00 = __expf(sf[nt][0] - mn0);
            float p01 = __expf(sf[nt][1] - mn0);
            float p10 = __expf(sf[nt][2] - mn1);
            float p11 = __expf(sf[nt][3] - mn1);
            s0 += p00 + p01;
            s1 += p10 + p11;
            int cc = nt * 8 + 2 * tg;
            sP[(qw + g    ) * ATP + cc    ] = f2tf(p00);
            sP[(qw + g    ) * ATP + cc + 1] = f2tf(p01);
            sP[(qw + g + 8) * ATP + cc    ] = f2tf(p10);
            sP[(qw + g + 8) * ATP + cc + 1] = f2tf(p11);
        }
        s0 += __shfl_xor_sync(0xffffffffu, s0, 1);
        s0 += __shfl_xor_sync(0xffffffffu, s0, 2);
        s1 += __shfl_xor_sync(0xffffffffu, s1, 1);
        s1 += __shfl_xor_sync(0xffffffffu, s1, 2);
        l0 = l0 * c0 + s0;
        l1 = l1 * c1 + s1;

        #pragma unroll
        for (int nt = 0; nt < 8; nt++) {
            oacc[nt][0] *= c0; oacc[nt][1] *= c0;
            oacc[nt][2] *= c1; oacc[nt][3] *= c1;
        }
        __syncwarp();   // sP rows are warp-private

        // O += P @ V
        #pragma unroll
        for (int kk = 0; kk < 8; kk++) {
            u32 af[4];
            af[0] = sP[(qw + g    ) * ATP + kk * 8 + tg];
            af[1] = sP[(qw + g + 8) * ATP + kk * 8 + tg];
            af[2] = sP[(qw + g    ) * ATP + kk * 8 + tg + 4];
            af[3] = sP[(qw + g + 8) * ATP + kk * 8 + tg + 4];
            #pragma unroll
            for (int nt = 0; nt < 8; nt++) {
                u32 bf[2];
                bf[0] = sV[(kk * 8 + tg    ) * ATP + nt * 8 + g];
                bf[1] = sV[(kk * 8 + tg + 4) * ATP + nt * 8 + g];
                mma_tf32(oacc[nt], af, bf);
            }
        }
    }

    // Normalize + write out as [B, S, DM]
    const int b = bh >> 4;
    const int h = bh & 15;
    const float inv0 = 1.0f / l0;
    const float inv1 = 1.0f / l1;
    #pragma unroll
    for (int nt = 0; nt < 8; nt++) {
        int col = h * HD + nt * 8 + 2 * tg;
        *(float2*)(O + ((size_t)(b * SEQ + q0g)) * DM + col) =
            make_float2(oacc[nt][0] * inv0, oacc[nt][1] * inv0);
        *(float2*)(O + ((size_t)(b * SEQ + q1g)) * DM + col) =
            make_float2(oacc[nt][2] * inv1, oacc[nt][3] * inv1);
    }
}

// ---------------------------------------------------------------------------
extern "C" void kernel_launch(void* const* d_in, const int* in_sizes, int n_in,
                              void* d_out, int out_size)
{
    const float* qw = (const float*)d_in[0];
    const float* kw = (const float*)d_in[1];
    const float* vw = (const float*)d_in[2];
    const float* ow = (const float*)d_in[3];
    const float* x  = (const float*)d_in[4];
    float* out = (float*)d_out;

    float *Qp, *Kp, *Vp, *AOp;
    cudaGetSymbolAddress((void**)&Qp,  g_Q);
    cudaGetSymbolAddress((void**)&Kp,  g_K);
    cudaGetSymbolAddress((void**)&Vp,  g_V);
    cudaGetSymbolAddress((void**)&AOp, g_AO);

    cudaFuncSetAttribute(attn_k, cudaFuncAttributeMaxDynamicSharedMemorySize,
                         ATTN_SMEM);

    dim3 gq(DM/128, MTOT/128, 3);   // (8, 64, 3)
    gemm_qkv<<<gq, 256>>>(x, qw, kw, vw, Qp, Kp, Vp);

    attn_k<<<dim3(SEQ/128, BATCH*NH), 256, ATTN_SMEM>>>(Qp, Kp, Vp, AOp);

    dim3 gg(DM/128, MTOT/128);      // (8, 64)
    gemm_o<<<gg, 256>>>(AOp, ow, out);
}